// round 3
// baseline (speedup 1.0000x reference)
#include <cuda_runtime.h>
#include <cstdint>

// Soft-DTW (gamma=1), 64 batches of 1024x1024.
// 2-CTA cluster per batch: CTA rank 0 owns rows 0..511, rank 1 rows 512..1023.
// Anti-diagonal wavefront, one thread per row within each CTA.
// Cross-CTA boundary (row 511 -> row 512) streamed one value per diagonal via
// a tagged 64-bit DSMEM ring (single atomic st.shared::cluster, tag = y+1).
// Log2-domain softmin with min/mid/max => 2x ex2 + 1x lg2 per cell.
// Out-of-range cells get huge-but-finite values via sentinel contour padding.

#define NBATCH 64
#define NPTS   1024
#define HALF   512
#define BIGV   1.0e30f
#define SENT   1.0e17f

__device__ float g_partial[NBATCH];

__device__ __forceinline__ float ex2f(float x) {
    float r; asm("ex2.approx.ftz.f32 %0, %1;" : "=f"(r) : "f"(x)); return r;
}
__device__ __forceinline__ float lg2f(float x) {
    float r; asm("lg2.approx.ftz.f32 %0, %1;" : "=f"(r) : "f"(x)); return r;
}
__device__ __forceinline__ uint32_t smem_u32(const void* p) {
    uint32_t a;
    asm("{ .reg .u64 t; cvta.to.shared.u64 t, %1; cvt.u32.u64 %0, t; }"
        : "=r"(a) : "l"(p));
    return a;
}

__global__ __launch_bounds__(HALF, 1) __cluster_dims__(2, 1, 1)
void dtw_kernel(const float* __restrict__ snake, const float* __restrict__ contour)
{
    __shared__ float2 scp[NPTS + 2];          // padded, scaled contour
    __shared__ float  buf[2][HALF];           // double-buffered diagonal
    __shared__ unsigned long long ring[2048]; // tagged boundary ring (rank 1 uses own copy)

    const int i = threadIdx.x;
    uint32_t rank; asm("mov.u32 %0, %%cluster_ctarank;" : "=r"(rank));
    const int b    = blockIdx.x >> 1;
    const int half = (int)rank;
    const int row  = half * HALF + i;
    const float SCALE = 1.2011224087864498f;  // sqrt(log2(e))

    // Load full scaled contour into shared (both halves sweep all columns).
    float2 c0 = ((const float2*)contour)[b * NPTS + i];
    scp[1 + i] = make_float2(c0.x * SCALE, c0.y * SCALE);
    float2 c1 = ((const float2*)contour)[b * NPTS + HALF + i];
    scp[1 + HALF + i] = make_float2(c1.x * SCALE, c1.y * SCALE);
    if (i == 0) {
        scp[0]        = make_float2(SENT, SENT);
        scp[NPTS + 1] = make_float2(SENT, SENT);
    }

    float2 s2 = ((const float2*)snake)[b * NPTS + row];
    const float sx = s2.x * SCALE, sy = s2.y * SCALE;

    // Rank 1 invalidates its ring tags before rank 0 may publish.
    if (half == 1) {
        for (int k = i; k < 2048; k += HALF) ring[k] = 0ULL;
    }
    __syncthreads();
    asm volatile("barrier.cluster.arrive.aligned;" ::: "memory");
    asm volatile("barrier.cluster.wait.aligned;" ::: "memory");

    float cur, nbprev = BIGV;
    int y0, y1;
    if (half == 0) {
        // Diagonal 0: only cell (0,0).
        if (i == 0) {
            float dx = sx - scp[1].x, dy = sy - scp[1].y;
            cur = fmaf(dy, dy, dx * dx);
        } else cur = BIGV;
        y0 = 1;   y1 = 1534;   // last diagonal touching rows 0..511
    } else {
        cur = BIGV;
        y0 = 512; y1 = 2046;   // first diagonal touching row 512
    }
    buf[0][i] = cur;
    buf[1][i] = cur;
    __syncthreads();

    int jp = y0 - row + 1;     // j + 1, advances with y
    for (int y = y0; y <= y1; ++y, ++jp) {
        // Up-neighbor value (row-1, one diagonal ago).
        float nb;
        if (i == 0) {
            if (half == 0) {
                nb = BIGV;
            } else if (y - 1 <= 1534) {
                uint32_t addr = smem_u32(&ring[y - 1]);
                unsigned long long p;
                do {
                    asm volatile("ld.volatile.shared.u64 %0, [%1];" : "=l"(p) : "r"(addr));
                } while ((unsigned)p != (unsigned)y);   // tag = (y-1)+1
                nb = __uint_as_float((uint32_t)(p >> 32));
            } else {
                nb = BIGV;  // row 511 invalid beyond diagonal 1534
            }
        } else {
            nb = buf[(y - 1) & 1][i - 1];
        }

        // Distance (sentinel padding makes out-of-range cells huge, no mask).
        int jc = min(max(jp, 0), NPTS + 1);
        float2 c = scp[jc];
        float dx = sx - c.x, dy = sy - c.y;
        float Dl = fmaf(dy, dy, dx * dx);

        // softmin via min/mid/max: one exp arg is 0 -> only 2 ex2 + 1 lg2.
        float t1  = fminf(nbprev, nb);
        float t2  = fmaxf(nbprev, nb);
        float mn  = fminf(t1, cur);
        float mx  = fmaxf(t2, cur);
        float mid = fminf(t2, fmaxf(t1, cur));
        float s   = 1.0f + ex2f(mn - mid) + ex2f(mn - mx);
        cur = Dl + (mn - lg2f(s));

        nbprev = nb;
        buf[y & 1][i] = cur;

        // Rank 0's top thread streams the boundary to rank 1's ring.
        if (half == 0 && i == HALF - 1 && y >= 511) {
            unsigned long long p =
                ((unsigned long long)__float_as_uint(cur) << 32) | (unsigned)(y + 1);
            uint32_t laddr = smem_u32(&ring[y]);
            uint32_t raddr;
            asm("mapa.shared::cluster.u32 %0, %1, %2;" : "=r"(raddr) : "r"(laddr), "r"(1));
            asm volatile("st.shared::cluster.u64 [%0], %1;" :: "r"(raddr), "l"(p) : "memory");
        }
        __syncthreads();
    }

    if (half == 1 && i == HALF - 1) {
        g_partial[b] = cur * 0.69314718055994531f;  // log2 -> ln
    }

    // Keep the cluster alive until the consumer is done with DSMEM.
    asm volatile("barrier.cluster.arrive.aligned;" ::: "memory");
    asm volatile("barrier.cluster.wait.aligned;" ::: "memory");
}

__global__ void reduce_kernel(float* __restrict__ out)
{
    float v = g_partial[threadIdx.x] + g_partial[threadIdx.x + 32];
    #pragma unroll
    for (int off = 16; off > 0; off >>= 1)
        v += __shfl_down_sync(0xFFFFFFFFu, v, off);
    if (threadIdx.x == 0)
        out[0] = v * (1.0f / NBATCH);
}

extern "C" void kernel_launch(void* const* d_in, const int* in_sizes, int n_in,
                              void* d_out, int out_size)
{
    const float* snake   = (const float*)d_in[0];
    const float* contour = (const float*)d_in[1];
    float* out = (float*)d_out;

    dtw_kernel<<<NBATCH * 2, HALF>>>(snake, contour);
    reduce_kernel<<<1, 32>>>(out);
}